// round 12
// baseline (speedup 1.0000x reference)
#include <cuda_runtime.h>
#include <cuda_fp16.h>
#include <math.h>
#include <stdint.h>

#define L_   12
#define S_   512
#define B_   4
#define DIN_ 768
#define D_   1024
#define H_   16
#define F_   4096
#define HD_  64
#define SB_  2048
#define BH_  (B_*H_)
#define DD_  (D_*D_)
#define DF_  (D_*F_)

typedef __half f16;

// ---------------- persistent scratch (device globals) ----------------
__device__ __align__(16) f16 g_wqkv_h[(size_t)L_*3*DD_];
__device__ __align__(16) f16 g_wo_h  [(size_t)L_*DD_];
__device__ __align__(16) f16 g_w1_h  [(size_t)L_*DF_];
__device__ __align__(16) f16 g_w2_h  [(size_t)L_*DF_];
__device__ __align__(16) f16 g_wp_h  [DIN_*D_];
__device__ float g_bqkv[L_*3*D_];
__device__ __align__(16) f16 g_seg_h[SB_*DIN_];
__device__ __align__(16) f16 g_seg_l[SB_*DIN_];
__device__ __align__(16) f16 g_hh[SB_*D_];
__device__ __align__(16) f16 g_hl[SB_*D_];
__device__ __align__(16) f16 g_ah[SB_*D_];
__device__ __align__(16) f16 g_al[SB_*D_];
__device__ __align__(16) f16 g_ffh[(size_t)SB_*F_];
__device__ __align__(16) f16 g_ffl[(size_t)SB_*F_];
__device__ __align__(16) f16 g_qh[SB_*D_];
__device__ __align__(16) f16 g_ql[SB_*D_];
__device__ __align__(16) f16 g_kh[SB_*D_];
__device__ __align__(16) f16 g_vh[SB_*D_];
__device__ unsigned char g_mask8[B_*S_];
__device__ int   g_mask_mode;
__device__ int   g_cnt[16];            // zero-init; self-resetting per use

// ============================================================================
// helpers
// ============================================================================
__device__ __forceinline__ uint32_t smem_u32(const void* p) {
    uint32_t a;
    asm("{ .reg .u64 t; cvta.to.shared.u64 t, %1; cvt.u32.u64 %0, t; }"
        : "=r"(a) : "l"(p));
    return a;
}
__device__ __forceinline__ void ldsm4(uint32_t* r, uint32_t addr) {
    asm volatile("ldmatrix.sync.aligned.m8n8.x4.shared.b16 {%0,%1,%2,%3}, [%4];"
                 : "=r"(r[0]), "=r"(r[1]), "=r"(r[2]), "=r"(r[3]) : "r"(addr));
}
__device__ __forceinline__ void ldsm4t(uint32_t* r, uint32_t addr) {
    asm volatile("ldmatrix.sync.aligned.m8n8.x4.trans.shared.b16 {%0,%1,%2,%3}, [%4];"
                 : "=r"(r[0]), "=r"(r[1]), "=r"(r[2]), "=r"(r[3]) : "r"(addr));
}
__device__ __forceinline__ void mma16816(float* d, const uint32_t* a, const uint32_t* b) {
    asm volatile(
        "mma.sync.aligned.m16n8k16.row.col.f32.f16.f16.f32 "
        "{%0,%1,%2,%3}, {%4,%5,%6,%7}, {%8,%9}, {%0,%1,%2,%3};"
        : "+f"(d[0]), "+f"(d[1]), "+f"(d[2]), "+f"(d[3])
        : "r"(a[0]), "r"(a[1]), "r"(a[2]), "r"(a[3]), "r"(b[0]), "r"(b[1]));
}
#define CP_ASYNC(dst, src) \
    asm volatile("cp.async.cg.shared.global [%0], [%1], 16;" :: "r"(dst), "l"(src))
#define CP_COMMIT() asm volatile("cp.async.commit_group;")
#define CP_WAIT(n)  asm volatile("cp.async.wait_group %0;" :: "n"(n))

__device__ __forceinline__ void split2(float v0, float v1, uint32_t& hi, uint32_t& lo) {
    __half2 h = __floats2half2_rn(v0, v1);
    __half2 l = __floats2half2_rn(v0 - __half2float(h.x), v1 - __half2float(h.y));
    hi = *(uint32_t*)&h; lo = *(uint32_t*)&l;
}
__device__ __forceinline__ uint32_t pack2h(float v0, float v1) {
    __half2 h = __floats2half2_rn(v0, v1);
    return *(uint32_t*)&h;
}

// ============================================================================
// conversions (vectorized x4)
// ============================================================================
__global__ void conv_split4(const float4* __restrict__ src, f16* __restrict__ dh,
                            f16* __restrict__ dl, int n4) {
    int i = blockIdx.x * blockDim.x + threadIdx.x;
    if (i >= n4) return;
    float4 v = src[i];
    uint32_t h01, l01, h23, l23;
    split2(v.x, v.y, h01, l01);
    split2(v.z, v.w, h23, l23);
    *(uint2*)(dh + (size_t)i * 4) = make_uint2(h01, h23);
    *(uint2*)(dl + (size_t)i * 4) = make_uint2(l01, l23);
}
__global__ void conv_hi4(const float4* __restrict__ src, f16* __restrict__ dh,
                         int n4, int inner4, int gm, int go) {
    int i = blockIdx.x * blockDim.x + threadIdx.x;
    if (i >= n4) return;
    float4 v = src[i];
    size_t d = ((size_t)(i / inner4) * inner4 * gm + (size_t)go * inner4 + (i % inner4)) * 4;
    *(uint2*)(dh + d) = make_uint2(pack2h(v.x, v.y), pack2h(v.z, v.w));
}
__global__ void map_bias(const float* __restrict__ src, float* __restrict__ dst,
                         int n, int inner, int gm, int go) {
    int i = blockIdx.x * blockDim.x + threadIdx.x;
    if (i >= n) return;
    dst[(size_t)(i / inner) * inner * gm + (size_t)go * inner + (i % inner)] = src[i];
}

// ---------------- mask: detect dtype, canonicalize to u8 ----------------
__global__ void detect_mask_kernel(const void* m) {
    __shared__ int flags[2];
    if (threadIdx.x == 0) { flags[0] = 0; flags[1] = 0; }
    __syncthreads();
    unsigned v = ((const unsigned*)m)[threadIdx.x];
    if (v > 1u) flags[0] = 1;
    if (v != 0u && v != 0x3F800000u) flags[1] = 1;
    __syncthreads();
    if (threadIdx.x == 0)
        g_mask_mode = (!flags[0]) ? 1 : ((!flags[1]) ? 2 : 0);
}
__global__ void mask8_kernel(const void* m) {
    int i = blockIdx.x * blockDim.x + threadIdx.x;
    int mode = g_mask_mode;
    unsigned char r;
    if (mode == 1)      r = ((const int*)m)[i] != 0;
    else if (mode == 2) r = ((const float*)m)[i] != 0.f;
    else                r = ((const unsigned char*)m)[i] != 0;
    g_mask8[i] = r;
}

// ============================================================================
// fp16 2-term HMMA GEMM: C = A[M,K] @ W[K,N], A split (h+l), W hi only.
// MODE 0: C = acc+bias            MODE 1: C += acc+bias
// MODE 2: CH/CL = split(gelu(acc+bias))
// MODE 3: QKV: z=0 rope->qh/ql, z=1 rope->kh, z=2 ->vh
// MODE 4: C += acc+bias, then last CTA per 128-row block computes LN -> CH/CL
// ============================================================================
#define A_STRIDE   80
#define B_STRIDE   272
#define AH_OFF     0
#define AL_OFF     10240
#define BH_OFF     20480
#define STAGE_B    29184
#define GEMM_SMEM  (2*STAGE_B)

__device__ __forceinline__ void load_stage(
    const f16* __restrict__ AH, const f16* __restrict__ AL,
    const f16* __restrict__ WH,
    int K, int N, int rowBase, int colBase, int ck, uint32_t st, int tid)
{
#pragma unroll
    for (int t = 0; t < 4; t++) {
        int idx = tid + t * 256;
        int tile = idx >> 9;
        int r = (idx >> 2) & 127;
        int c16 = idx & 3;
        const f16* src = (tile ? AL : AH) + (size_t)(rowBase + r) * K + ck + c16 * 8;
        uint32_t dst = st + (tile ? AL_OFF : AH_OFF) + r * A_STRIDE + c16 * 16;
        CP_ASYNC(dst, src);
    }
#pragma unroll
    for (int t = 0; t < 2; t++) {
        int idx = tid + t * 256;
        int r = (idx >> 4) & 31;
        int c16 = idx & 15;
        const f16* src = WH + (size_t)(ck + r) * N + colBase + c16 * 8;
        uint32_t dst = st + BH_OFF + r * B_STRIDE + c16 * 16;
        CP_ASYNC(dst, src);
    }
}

template<int MODE>
__global__ void __launch_bounds__(256, 2) hmma2(
    const f16* __restrict__ AH, const f16* __restrict__ AL,
    const f16* __restrict__ WH,
    const float* __restrict__ bias, float* __restrict__ C,
    f16* __restrict__ CH, f16* __restrict__ CL,
    f16* __restrict__ o1h, f16* __restrict__ o2h,
    const float* __restrict__ lng, const float* __restrict__ lnb,
    int M, int N, int K, long long Wz, long long bz)
{
    extern __shared__ char smem[];
    const int z = blockIdx.z;
    WH += (size_t)z * Wz; bias += (size_t)z * bz;

    const int tid  = threadIdx.x;
    const int lane = tid & 31;
    const int wid  = tid >> 5;
    const int m0   = (wid & 3) << 5;
    const int n0w  = (wid >> 2) << 6;
    const int rowBase = blockIdx.y << 7;
    const int colBase = blockIdx.x << 7;
    const int NC = K >> 5;

    uint32_t sbase = smem_u32(smem);

    float acc[2][8][4];
#pragma unroll
    for (int a = 0; a < 2; a++)
#pragma unroll
        for (int b = 0; b < 8; b++)
#pragma unroll
            for (int c = 0; c < 4; c++) acc[a][b][c] = 0.f;

    load_stage(AH, AL, WH, K, N, rowBase, colBase, 0, sbase, tid);
    CP_COMMIT();
    load_stage(AH, AL, WH, K, N, rowBase, colBase, 32, sbase + STAGE_B, tid);
    CP_COMMIT();
    CP_WAIT(1);
    __syncthreads();

    const int arow = lane & 15;
    const int aoff = (lane >> 4) << 4;

    for (int c = 0; c < NC; c++) {
        uint32_t cur = sbase + (c & 1) * STAGE_B;
#pragma unroll
        for (int ks = 0; ks < 32; ks += 16) {
            uint32_t ah[2][4], al[2][4];
#pragma unroll
            for (int mt = 0; mt < 2; mt++) {
                uint32_t ad = cur + (uint32_t)((m0 + mt * 16 + arow) * A_STRIDE + ks * 2 + aoff);
                ldsm4(ah[mt], ad);
                ldsm4(al[mt], ad + AL_OFF);
            }
#pragma unroll
            for (int np = 0; np < 4; np++) {
                uint32_t bh[4];
                uint32_t bd = cur + BH_OFF +
                    (uint32_t)((ks + arow) * B_STRIDE + ((n0w + np * 16) << 1) + aoff);
                ldsm4t(bh, bd);
#pragma unroll
                for (int mt = 0; mt < 2; mt++)
#pragma unroll
                    for (int e = 0; e < 2; e++) {
                        uint32_t bfh[2] = { bh[2 * e], bh[2 * e + 1] };
                        float* d = acc[mt][np * 2 + e];
                        mma16816(d, ah[mt], bfh);
                        mma16816(d, al[mt], bfh);
                    }
            }
        }
        __syncthreads();
        if (c + 2 < NC) {
            load_stage(AH, AL, WH, K, N, rowBase, colBase, (c + 2) << 5,
                       sbase + (c & 1) * STAGE_B, tid);
            CP_COMMIT();
            CP_WAIT(1);
        } else {
            CP_WAIT(0);
        }
        __syncthreads();
    }

    // ---- epilogue ----
    if (MODE == 3) {
#pragma unroll
        for (int mt = 0; mt < 2; mt++) {
#pragma unroll
            for (int half = 0; half < 2; half++) {
                const int row = rowBase + m0 + mt * 16 + (lane >> 2) + half * 8;
                const int s = row >> 2;
                if (z < 2) {
#pragma unroll
                    for (int nt = 0; nt < 4; nt++) {
                        const int c0 = colBase + n0w + (nt << 3) + ((lane & 3) << 1);
                        float v0 = acc[mt][nt][half * 2 + 0] + bias[c0];
                        float v1 = acc[mt][nt][half * 2 + 1] + bias[c0 + 1];
                        float w0 = acc[mt][nt + 4][half * 2 + 0] + bias[c0 + 32];
                        float w1 = acc[mt][nt + 4][half * 2 + 1] + bias[c0 + 33];
                        int i0 = c0 & 63;
                        float th0 = (float)s * expf(-0.28782313662425572f * (float)i0);
                        float th1 = (float)s * expf(-0.28782313662425572f * (float)(i0 + 1));
                        float c0s, s0s, c1s, s1s;
                        sincosf(th0, &s0s, &c0s);
                        sincosf(th1, &s1s, &c1s);
                        float y0 = v0 * c0s - w0 * s0s, zz0 = w0 * c0s + v0 * s0s;
                        float y1 = v1 * c1s - w1 * s1s, zz1 = w1 * c1s + v1 * s1s;
                        if (z == 0) {
                            uint32_t hi, lo;
                            split2(y0, y1, hi, lo);
                            *(uint32_t*)(CH + (size_t)row * D_ + c0) = hi;
                            *(uint32_t*)(CL + (size_t)row * D_ + c0) = lo;
                            split2(zz0, zz1, hi, lo);
                            *(uint32_t*)(CH + (size_t)row * D_ + c0 + 32) = hi;
                            *(uint32_t*)(CL + (size_t)row * D_ + c0 + 32) = lo;
                        } else {
                            *(uint32_t*)(o1h + (size_t)row * D_ + c0) = pack2h(y0, y1);
                            *(uint32_t*)(o1h + (size_t)row * D_ + c0 + 32) = pack2h(zz0, zz1);
                        }
                    }
                } else {
#pragma unroll
                    for (int nt = 0; nt < 8; nt++) {
                        const int c0 = colBase + n0w + (nt << 3) + ((lane & 3) << 1);
                        float v0 = acc[mt][nt][half * 2 + 0] + bias[c0];
                        float v1 = acc[mt][nt][half * 2 + 1] + bias[c0 + 1];
                        *(uint32_t*)(o2h + (size_t)row * D_ + c0) = pack2h(v0, v1);
                    }
                }
            }
        }
        return;
    }

#pragma unroll
    for (int mt = 0; mt < 2; mt++) {
        const int r0 = rowBase + m0 + mt * 16 + (lane >> 2);
#pragma unroll
        for (int nt = 0; nt < 8; nt++) {
            const int c0 = colBase + n0w + nt * 8 + ((lane & 3) << 1);
            float* d = acc[mt][nt];
            float b0 = bias[c0], b1 = bias[c0 + 1];
#pragma unroll
            for (int half = 0; half < 2; half++) {
                const int row = r0 + half * 8;
                float v0 = d[half * 2 + 0] + b0;
                float v1 = d[half * 2 + 1] + b1;
                if (MODE == 0) {
                    float* out = C + (size_t)row * N + c0;
                    out[0] = v0; out[1] = v1;
                } else if (MODE == 1 || MODE == 4) {
                    float* out = C + (size_t)row * N + c0;
                    out[0] += v0; out[1] += v1;
                } else {
                    float g0 = 0.5f * v0 * (1.f + erff(v0 * 0.70710678118654752f));
                    float g1 = 0.5f * v1 * (1.f + erff(v1 * 0.70710678118654752f));
                    uint32_t hi, lo;
                    split2(g0, g1, hi, lo);
                    *(uint32_t*)(CH + (size_t)row * N + c0) = hi;
                    *(uint32_t*)(CL + (size_t)row * N + c0) = lo;
                }
            }
        }
    }

    if (MODE == 4) {
        // release: make this CTA's x-tile visible, then count arrivals
        __threadfence();
        __syncthreads();
        __shared__ int lastFlag;
        if (tid == 0) {
            int old = atomicAdd(&g_cnt[blockIdx.y], 1);
            int last = (old == (int)gridDim.x - 1);
            if (last) atomicExch(&g_cnt[blockIdx.y], 0);
            lastFlag = last;
        }
        __syncthreads();
        if (!lastFlag) return;
        __threadfence();   // acquire: other CTAs' x writes now visible

        // LN over rows [rowBase, rowBase+128), D=1024; warp per row, 16 rows/warp
        for (int i = 0; i < 16; i++) {
            const int row = rowBase + wid * 16 + i;
            const float* xr = C + (size_t)row * D_;
            float4 vv[8];
            float s = 0.f, s2 = 0.f;
#pragma unroll
            for (int k2 = 0; k2 < 8; k2++) {
                vv[k2] = *(const float4*)(xr + lane * 4 + k2 * 128);
                s  += vv[k2].x + vv[k2].y + vv[k2].z + vv[k2].w;
                s2 += vv[k2].x * vv[k2].x + vv[k2].y * vv[k2].y
                    + vv[k2].z * vv[k2].z + vv[k2].w * vv[k2].w;
            }
#pragma unroll
            for (int o = 16; o; o >>= 1) {
                s  += __shfl_xor_sync(0xFFFFFFFFu, s,  o);
                s2 += __shfl_xor_sync(0xFFFFFFFFu, s2, o);
            }
            float mean = s * (1.f / D_);
            float var  = s2 * (1.f / D_) - mean * mean;
            float rstd = rsqrtf(var + 1e-5f);
#pragma unroll
            for (int k2 = 0; k2 < 8; k2++) {
                int c0 = lane * 4 + k2 * 128;
                float4 gv = *(const float4*)(lng + c0);
                float4 bv = *(const float4*)(lnb + c0);
                float o0 = (vv[k2].x - mean) * rstd * gv.x + bv.x;
                float o1 = (vv[k2].y - mean) * rstd * gv.y + bv.y;
                float o2 = (vv[k2].z - mean) * rstd * gv.z + bv.z;
                float o3 = (vv[k2].w - mean) * rstd * gv.w + bv.w;
                uint32_t h01, l01, h23, l23;
                split2(o0, o1, h01, l01);
                split2(o2, o3, h23, l23);
                *(uint2*)(CH + (size_t)row * D_ + c0) = make_uint2(h01, h23);
                *(uint2*)(CL + (size_t)row * D_ + c0) = make_uint2(l01, l23);
            }
        }
    }
}

// ============================================================================
// Flash attention (fp16 2-term): Q split, K/V hi-only.
// ============================================================================
#define FA_STRIDE 144
#define FA_TILE   18432
#define FA_SMEM   (6*FA_TILE)

__device__ __forceinline__ void fa_kv_load(
    const f16* __restrict__ kh, const f16* __restrict__ vh,
    size_t hoff, int krow0, uint32_t dst, int tid)
{
#pragma unroll
    for (int t = 0; t < 8; t++) {
        int idx = tid + t * 256;
        int tile = idx >> 10, rem = idx & 1023;
        int r = rem >> 3, c = rem & 7;
        const f16* base = tile ? vh : kh;
        const f16* src = base + hoff + (size_t)(krow0 + r) * (B_ * D_) + c * 8;
        CP_ASYNC(dst + tile * FA_TILE + r * FA_STRIDE + c * 16, src);
    }
}

__global__ void __launch_bounds__(256, 1) flash_attn(
    const f16* __restrict__ qh, const f16* __restrict__ ql,
    const f16* __restrict__ kh, const f16* __restrict__ vh,
    const unsigned char* __restrict__ mask8,
    f16* __restrict__ aH, f16* __restrict__ aL)
{
    extern __shared__ char smem[];
    const int bh = blockIdx.y;
    const int b = bh >> 4, h = bh & 15;
    const int q0 = blockIdx.x << 7;
    const int tid = threadIdx.x, lane = tid & 31, wid = tid >> 5;
    const int m0 = wid << 4;
    const size_t hoff = (size_t)b * D_ + h * HD_;
    uint32_t sb = smem_u32(smem);
    const uint32_t kv0 = sb + 2 * FA_TILE;
    const uint32_t kv1 = sb + 4 * FA_TILE;

#pragma unroll
    for (int t = 0; t < 8; t++) {
        int idx = tid + t * 256;
        int tile = idx >> 10, rem = idx & 1023;
        int r = rem >> 3, c = rem & 7;
        const f16* src = (tile ? ql : qh) + hoff + (size_t)(q0 + r) * (B_ * D_) + c * 8;
        CP_ASYNC(sb + tile * FA_TILE + r * FA_STRIDE + c * 16, src);
    }
    fa_kv_load(kh, vh, hoff, 0, kv0, tid);
    CP_COMMIT();
    fa_kv_load(kh, vh, hoff, 128, kv1, tid);
    CP_COMMIT();
    CP_WAIT(1);
    __syncthreads();

    float oacc[8][4];
#pragma unroll
    for (int i = 0; i < 8; i++)
#pragma unroll
        for (int j = 0; j < 4; j++) oacc[i][j] = 0.f;
    float mr0 = -1e30f, mr1 = -1e30f, l0 = 0.f, l1 = 0.f;

    const int arow = lane & 15;
    const int aoff = (lane >> 4) << 4;
    const unsigned char* mrow = mask8 + b * S_;

    for (int kt = 0; kt < 4; kt++) {
        const uint32_t kv = (kt & 1) ? kv1 : kv0;
        float sacc[16][4];
#pragma unroll
        for (int i = 0; i < 16; i++)
#pragma unroll
            for (int j = 0; j < 4; j++) sacc[i][j] = 0.f;

#pragma unroll
        for (int kc = 0; kc < 4; kc++) {
            uint32_t qa = sb + (uint32_t)((m0 + arow) * FA_STRIDE + kc * 32 + aoff);
            uint32_t qhf[4], qlf[4];
            ldsm4(qhf, qa);
            ldsm4(qlf, qa + FA_TILE);
#pragma unroll
            for (int ng = 0; ng < 8; ng++) {
                uint32_t bhf[4];
                uint32_t ka = kv + (uint32_t)((ng * 16 + arow) * FA_STRIDE + kc * 32 + aoff);
                ldsm4(bhf, ka);
#pragma unroll
                for (int e = 0; e < 2; e++) {
                    uint32_t bh2[2] = { bhf[e], bhf[e + 2] };
                    float* d = sacc[ng * 2 + e];
                    mma16816(d, qhf, bh2);
                    mma16816(d, qlf, bh2);
                }
            }
        }

        float mx0 = -1e30f, mx1 = -1e30f;
#pragma unroll
        for (int nt = 0; nt < 16; nt++) {
#pragma unroll
            for (int u = 0; u < 2; u++) {
                int col = (kt << 7) + (nt << 3) + ((lane & 3) << 1) + u;
                bool msk = mrow[col] != 0;
                float v0 = msk ? -1e30f : sacc[nt][u] * 0.125f;
                float v1 = msk ? -1e30f : sacc[nt][2 + u] * 0.125f;
                sacc[nt][u] = v0; sacc[nt][2 + u] = v1;
                mx0 = fmaxf(mx0, v0); mx1 = fmaxf(mx1, v1);
            }
        }
        mx0 = fmaxf(mx0, __shfl_xor_sync(0xFFFFFFFFu, mx0, 1));
        mx0 = fmaxf(mx0, __shfl_xor_sync(0xFFFFFFFFu, mx0, 2));
        mx1 = fmaxf(mx1, __shfl_xor_sync(0xFFFFFFFFu, mx1, 1));
        mx1 = fmaxf(mx1, __shfl_xor_sync(0xFFFFFFFFu, mx1, 2));
        float mn0 = fmaxf(mr0, mx0), mn1 = fmaxf(mr1, mx1);
        float al0 = __expf(mr0 - mn0), al1 = __expf(mr1 - mn1);
        mr0 = mn0; mr1 = mn1;

        float s0 = 0.f, s1 = 0.f;
#pragma unroll
        for (int nt = 0; nt < 16; nt++) {
            float p0 = __expf(sacc[nt][0] - mn0);
            float p1 = __expf(sacc[nt][1] - mn0);
            float p2 = __expf(sacc[nt][2] - mn1);
            float p3 = __expf(sacc[nt][3] - mn1);
            sacc[nt][0] = p0; sacc[nt][1] = p1; sacc[nt][2] = p2; sacc[nt][3] = p3;
            s0 += p0 + p1; s1 += p2 + p3;
        }
        s0 += __shfl_xor_sync(0xFFFFFFFFu, s0, 1);
        s0 += __shfl_xor_sync(0xFFFFFFFFu, s0, 2);
        s1 += __shfl_xor_sync(0xFFFFFFFFu, s1, 1);
        s1 += __shfl_xor_sync(0xFFFFFFFFu, s1, 2);
        l0 = l0 * al0 + s0;
        l1 = l1 * al1 + s1;
#pragma unroll
        for (int nt = 0; nt < 8; nt++) {
            oacc[nt][0] *= al0; oacc[nt][1] *= al0;
            oacc[nt][2] *= al1; oacc[nt][3] *= al1;
        }

#pragma unroll
        for (int kc2 = 0; kc2 < 8; kc2++) {
            uint32_t pa_h[4], pa_l[4];
            split2(sacc[2 * kc2][0],     sacc[2 * kc2][1],     pa_h[0], pa_l[0]);
            split2(sacc[2 * kc2][2],     sacc[2 * kc2][3],     pa_h[1], pa_l[1]);
            split2(sacc[2 * kc2 + 1][0], sacc[2 * kc2 + 1][1], pa_h[2], pa_l[2]);
            split2(sacc[2 * kc2 + 1][2], sacc[2 * kc2 + 1][3], pa_h[3], pa_l[3]);
#pragma unroll
            for (int ng = 0; ng < 4; ng++) {
                uint32_t bhf[4];
                uint32_t va = kv + FA_TILE +
                    (uint32_t)((kc2 * 16 + arow) * FA_STRIDE + ng * 32 + aoff);
                ldsm4t(bhf, va);
#pragma unroll
                for (int e = 0; e < 2; e++) {
                    uint32_t bh2[2] = { bhf[2 * e], bhf[2 * e + 1] };
                    float* d = oacc[ng * 2 + e];
                    mma16816(d, pa_h, bh2);
                    mma16816(d, pa_l, bh2);
                }
            }
        }

        __syncthreads();
        if (kt + 2 < 4) {
            fa_kv_load(kh, vh, hoff, (kt + 2) << 7, kv, tid);
            CP_COMMIT();
            CP_WAIT(1);
            __syncthreads();
        } else if (kt + 1 < 4) {
            CP_WAIT(0);
            __syncthreads();
        }
    }

    float inv0 = 1.f / l0, inv1 = 1.f / l1;
    const int r0 = q0 + m0 + (lane >> 2);
#pragma unroll
    for (int nt = 0; nt < 8; nt++) {
        const int c0 = (nt << 3) + ((lane & 3) << 1);
        uint32_t hi, lo;
        split2(oacc[nt][0] * inv0, oacc[nt][1] * inv0, hi, lo);
        size_t a0 = hoff + (size_t)r0 * (B_ * D_) + c0;
        *(uint32_t*)(aH + a0) = hi;
        *(uint32_t*)(aL + a0) = lo;
        split2(oacc[nt][2] * inv1, oacc[nt][3] * inv1, hi, lo);
        size_t a1 = hoff + (size_t)(r0 + 8) * (B_ * D_) + c0;
        *(uint32_t*)(aH + a1) = hi;
        *(uint32_t*)(aL + a1) = lo;
    }
}

// ---------------- LayerNorm -> split fp16 (only used for layer-0 LN1) -------
__global__ __launch_bounds__(256) void ln_kernel(
    const float* __restrict__ x, const float* __restrict__ g,
    const float* __restrict__ b, f16* __restrict__ outH, f16* __restrict__ outL)
{
    int row = blockIdx.x;
    int tid = threadIdx.x;
    const float* xr = x + (size_t)row * D_;
    float4 v = *(const float4*)(xr + tid * 4);
    float s  = v.x + v.y + v.z + v.w;
    float s2 = v.x * v.x + v.y * v.y + v.z * v.z + v.w * v.w;
    __shared__ float r1[256], r2[256];
    r1[tid] = s; r2[tid] = s2;
    __syncthreads();
    for (int off = 128; off > 0; off >>= 1) {
        if (tid < off) { r1[tid] += r1[tid + off]; r2[tid] += r2[tid + off]; }
        __syncthreads();
    }
    float mean = r1[0] * (1.f / D_);
    float var  = r2[0] * (1.f / D_) - mean * mean;
    float rstd = rsqrtf(var + 1e-5f);
    float4 gv = *(const float4*)(g + tid * 4);
    float4 bv = *(const float4*)(b + tid * 4);
    float o0 = (v.x - mean) * rstd * gv.x + bv.x;
    float o1 = (v.y - mean) * rstd * gv.y + bv.y;
    float o2 = (v.z - mean) * rstd * gv.z + bv.z;
    float o3 = (v.w - mean) * rstd * gv.w + bv.w;
    uint32_t h01, l01, h23, l23;
    split2(o0, o1, h01, l01);
    split2(o2, o3, h23, l23);
    size_t base = (size_t)row * D_ + tid * 4;
    *(uint2*)(outH + base) = make_uint2(h01, h23);
    *(uint2*)(outL + base) = make_uint2(l01, l23);
}

// ---------------- x += dur[r]*Wdur[c] + bdur[c] ----------------
__global__ void adddur_kernel(float* __restrict__ x, const float* __restrict__ dur,
                              const float* __restrict__ wd, const float* __restrict__ bd) {
    int idx = blockIdx.x * blockDim.x + threadIdx.x;
    int r = idx >> 10, c = idx & 1023;
    x[idx] += dur[r] * wd[c] + bd[c];
}

// ---------------- host orchestration ----------------
extern "C" void kernel_launch(void* const* d_in, const int* in_sizes, int n_in,
                              void* d_out, int out_size)
{
    (void)in_sizes; (void)n_in; (void)out_size;
    const float* segments  = (const float*)d_in[0];
    const float* durations = (const float*)d_in[1];
    const void*  mask      = d_in[2];
    const float* Wproj = (const float*)d_in[3];
    const float* bproj = (const float*)d_in[4];
    const float* Wdur  = (const float*)d_in[5];
    const float* bdur  = (const float*)d_in[6];
    const float* ln1g  = (const float*)d_in[7];
    const float* ln1b  = (const float*)d_in[8];
    const float* Wq    = (const float*)d_in[9];
    const float* bq    = (const float*)d_in[10];
    const float* Wk    = (const float*)d_in[11];
    const float* bk    = (const float*)d_in[12];
    const float* Wv    = (const float*)d_in[13];
    const float* bv    = (const float*)d_in[14];
    const float* Wo    = (const float*)d_in[15];
    const float* bo    = (const float*)d_in[16];
    const float* ln2g  = (const float*)d_in[17];
    const float* ln2b  = (const float*)d_in[18];
    const float* W1    = (const float*)d_in[19];
    const float* b1    = (const float*)d_in[20];
    const float* W2    = (const float*)d_in[21];
    const float* b2    = (const float*)d_in[22];
    float* x = (float*)d_out;

    f16 *wqkvH, *woH, *w1H, *w2H, *wpH;
    f16 *segH, *segL, *hH, *hL, *aH, *aL, *ffH, *ffL;
    f16 *qh, *ql, *kh, *vh;
    float *bqkv;
    unsigned char* mask8;
    cudaGetSymbolAddress((void**)&wqkvH, g_wqkv_h);
    cudaGetSymbolAddress((void**)&woH,   g_wo_h);
    cudaGetSymbolAddress((void**)&w1H,   g_w1_h);
    cudaGetSymbolAddress((void**)&w2H,   g_w2_h);
    cudaGetSymbolAddress((void**)&wpH,   g_wp_h);
    cudaGetSymbolAddress((void**)&segH,  g_seg_h);
    cudaGetSymbolAddress((void**)&segL,  g_seg_l);
    cudaGetSymbolAddress((void**)&hH,    g_hh);
    cudaGetSymbolAddress((void**)&hL,    g_hl);
    cudaGetSymbolAddress((void**)&aH,    g_ah);
    cudaGetSymbolAddress((void**)&aL,    g_al);
    cudaGetSymbolAddress((void**)&ffH,   g_ffh);
    cudaGetSymbolAddress((void**)&ffL,   g_ffl);
    cudaGetSymbolAddress((void**)&bqkv,  g_bqkv);
    cudaGetSymbolAddress((void**)&qh, g_qh);
    cudaGetSymbolAddress((void**)&ql, g_ql);
    cudaGetSymbolAddress((void**)&kh, g_kh);
    cudaGetSymbolAddress((void**)&vh, g_vh);
    cudaGetSymbolAddress((void**)&mask8, g_mask8);

    cudaFuncSetAttribute(hmma2<0>, cudaFuncAttributeMaxDynamicSharedMemorySize, GEMM_SMEM);
    cudaFuncSetAttribute(hmma2<1>, cudaFuncAttributeMaxDynamicSharedMemorySize, GEMM_SMEM);
    cudaFuncSetAttribute(hmma2<2>, cudaFuncAttributeMaxDynamicSharedMemorySize, GEMM_SMEM);
    cudaFuncSetAttribute(hmma2<3>, cudaFuncAttributeMaxDynamicSharedMemorySize, GEMM_SMEM);
    cudaFuncSetAttribute(hmma2<4>, cudaFuncAttributeMaxDynamicSharedMemorySize, GEMM_SMEM);
    cudaFuncSetAttribute(flash_attn, cudaFuncAttributeMaxDynamicSharedMemorySize, FA_SMEM);

    detect_mask_kernel<<<1, 512>>>(mask);
    mask8_kernel<<<8, 256>>>(mask);

    const int CT = 256;
    int n4;
    n4 = (L_ * DD_) / 4;
    conv_hi4<<<(n4 + CT - 1) / CT, CT>>>((const float4*)Wq, wqkvH, n4, DD_ / 4, 3, 0);
    conv_hi4<<<(n4 + CT - 1) / CT, CT>>>((const float4*)Wk, wqkvH, n4, DD_ / 4, 3, 1);
    conv_hi4<<<(n4 + CT - 1) / CT, CT>>>((const float4*)Wv, wqkvH, n4, DD_ / 4, 3, 2);
    conv_hi4<<<(n4 + CT - 1) / CT, CT>>>((const float4*)Wo, woH, n4, 1, 1, 0);
    n4 = (L_ * DF_) / 4;
    conv_hi4<<<(n4 + CT - 1) / CT, CT>>>((const float4*)W1, w1H, n4, 1, 1, 0);
    conv_hi4<<<(n4 + CT - 1) / CT, CT>>>((const float4*)W2, w2H, n4, 1, 1, 0);
    n4 = (DIN_ * D_) / 4;
    conv_hi4<<<(n4 + CT - 1) / CT, CT>>>((const float4*)Wproj, wpH, n4, 1, 1, 0);
    n4 = (SB_ * DIN_) / 4;
    conv_split4<<<(n4 + CT - 1) / CT, CT>>>((const float4*)segments, segH, segL, n4);
    int nb = L_ * D_;
    map_bias<<<(nb + CT - 1) / CT, CT>>>(bq, bqkv, nb, D_, 3, 0);
    map_bias<<<(nb + CT - 1) / CT, CT>>>(bk, bqkv, nb, D_, 3, 1);
    map_bias<<<(nb + CT - 1) / CT, CT>>>(bv, bqkv, nb, D_, 3, 2);

    dim3 gD(D_ / 128, SB_ / 128);
    dim3 gQKV(D_ / 128, SB_ / 128, 3);
    dim3 gF(F_ / 128, SB_ / 128);

    hmma2<0><<<gD, 256, GEMM_SMEM>>>(segH, segL, wpH, bproj, x,
        nullptr, nullptr, nullptr, nullptr, nullptr, nullptr, SB_, D_, DIN_, 0, 0);
    adddur_kernel<<<(SB_ * D_) / 256, 256>>>(x, durations, Wdur, bdur);

    for (int l = 0; l < L_; l++) {
        if (l == 0)
            ln_kernel<<<SB_, 256>>>(x, ln1g, ln1b, hH, hL);
        hmma2<3><<<gQKV, 256, GEMM_SMEM>>>(hH, hL,
            wqkvH + (size_t)l * 3 * DD_,
            bqkv + (size_t)l * 3 * D_, nullptr,
            qh, ql, kh, vh, nullptr, nullptr,
            SB_, D_, D_, DD_, D_);
        flash_attn<<<dim3(4, BH_), 256, FA_SMEM>>>(qh, ql, kh, vh, mask8, aH, aL);
        // Wo GEMM: residual into x, fused LN2 -> hH/hL
        hmma2<4><<<gD, 256, GEMM_SMEM>>>(aH, aL,
            woH + (size_t)l * DD_,
            bo + (size_t)l * D_, x,
            hH, hL, nullptr, nullptr,
            ln2g + (size_t)l * D_, ln2b + (size_t)l * D_,
            SB_, D_, D_, 0, 0);
        hmma2<2><<<gF, 256, GEMM_SMEM>>>(hH, hL,
            w1H + (size_t)l * DF_,
            b1 + (size_t)l * F_, nullptr,
            ffH, ffL, nullptr, nullptr, nullptr, nullptr, SB_, F_, D_, 0, 0);
        if (l + 1 < L_) {
            // FF2 GEMM: residual into x, fused LN1 of next layer -> hH/hL
            hmma2<4><<<gD, 256, GEMM_SMEM>>>(ffH, ffL,
                w2H + (size_t)l * DF_,
                b2 + (size_t)l * D_, x,
                hH, hL, nullptr, nullptr,
                ln1g + (size_t)(l + 1) * D_, ln1b + (size_t)(l + 1) * D_,
                SB_, D_, F_, 0, 0);
        } else {
            hmma2<1><<<gD, 256, GEMM_SMEM>>>(ffH, ffL,
                w2H + (size_t)l * DF_,
                b2 + (size_t)l * D_, x,
                nullptr, nullptr, nullptr, nullptr, nullptr, nullptr,
                SB_, D_, F_, 0, 0);
        }
    }
}

// round 14
// speedup vs baseline: 1.3088x; 1.3088x over previous
#include <cuda_runtime.h>
#include <cuda_fp16.h>
#include <math.h>
#include <stdint.h>

#define L_   12
#define S_   512
#define B_   4
#define DIN_ 768
#define D_   1024
#define H_   16
#define F_   4096
#define HD_  64
#define SB_  2048
#define BH_  (B_*H_)
#define DD_  (D_*D_)
#define DF_  (D_*F_)

typedef __half f16;

// ---------------- persistent scratch (device globals) ----------------
__device__ __align__(16) f16 g_wqkv_h[(size_t)L_*3*DD_];
__device__ __align__(16) f16 g_wo_h  [(size_t)L_*DD_];
__device__ __align__(16) f16 g_w1_h  [(size_t)L_*DF_];
__device__ __align__(16) f16 g_w2_h  [(size_t)L_*DF_];
__device__ __align__(16) f16 g_wp_h  [DIN_*D_];
__device__ float g_bqkv[L_*3*D_];
__device__ __align__(16) f16 g_seg_h[SB_*DIN_];
__device__ __align__(16) f16 g_seg_l[SB_*DIN_];
__device__ __align__(16) f16 g_hh[SB_*D_];
__device__ __align__(16) f16 g_hl[SB_*D_];
__device__ __align__(16) f16 g_ah[SB_*D_];
__device__ __align__(16) f16 g_al[SB_*D_];
__device__ __align__(16) f16 g_ffh[(size_t)SB_*F_];
__device__ __align__(16) f16 g_qh[SB_*D_];
__device__ __align__(16) f16 g_ql[SB_*D_];
__device__ __align__(16) f16 g_kh[SB_*D_];
__device__ __align__(16) f16 g_vh[SB_*D_];
__device__ unsigned char g_mask8[B_*S_];
__device__ int   g_mask_mode;

// ============================================================================
// helpers
// ============================================================================
__device__ __forceinline__ uint32_t smem_u32(const void* p) {
    uint32_t a;
    asm("{ .reg .u64 t; cvta.to.shared.u64 t, %1; cvt.u32.u64 %0, t; }"
        : "=r"(a) : "l"(p));
    return a;
}
__device__ __forceinline__ void ldsm4(uint32_t* r, uint32_t addr) {
    asm volatile("ldmatrix.sync.aligned.m8n8.x4.shared.b16 {%0,%1,%2,%3}, [%4];"
                 : "=r"(r[0]), "=r"(r[1]), "=r"(r[2]), "=r"(r[3]) : "r"(addr));
}
__device__ __forceinline__ void ldsm4t(uint32_t* r, uint32_t addr) {
    asm volatile("ldmatrix.sync.aligned.m8n8.x4.trans.shared.b16 {%0,%1,%2,%3}, [%4];"
                 : "=r"(r[0]), "=r"(r[1]), "=r"(r[2]), "=r"(r[3]) : "r"(addr));
}
__device__ __forceinline__ void mma16816(float* d, const uint32_t* a, const uint32_t* b) {
    asm volatile(
        "mma.sync.aligned.m16n8k16.row.col.f32.f16.f16.f32 "
        "{%0,%1,%2,%3}, {%4,%5,%6,%7}, {%8,%9}, {%0,%1,%2,%3};"
        : "+f"(d[0]), "+f"(d[1]), "+f"(d[2]), "+f"(d[3])
        : "r"(a[0]), "r"(a[1]), "r"(a[2]), "r"(a[3]), "r"(b[0]), "r"(b[1]));
}
#define CP_ASYNC(dst, src) \
    asm volatile("cp.async.cg.shared.global [%0], [%1], 16;" :: "r"(dst), "l"(src))
#define CP_COMMIT() asm volatile("cp.async.commit_group;")
#define CP_WAIT(n)  asm volatile("cp.async.wait_group %0;" :: "n"(n))

__device__ __forceinline__ void split2(float v0, float v1, uint32_t& hi, uint32_t& lo) {
    __half2 h = __floats2half2_rn(v0, v1);
    __half2 l = __floats2half2_rn(v0 - __half2float(h.x), v1 - __half2float(h.y));
    hi = *(uint32_t*)&h; lo = *(uint32_t*)&l;
}
__device__ __forceinline__ uint32_t pack2h(float v0, float v1) {
    __half2 h = __floats2half2_rn(v0, v1);
    return *(uint32_t*)&h;
}

// ============================================================================
// conversions (vectorized x4)
// ============================================================================
__global__ void conv_split4(const float4* __restrict__ src, f16* __restrict__ dh,
                            f16* __restrict__ dl, int n4) {
    int i = blockIdx.x * blockDim.x + threadIdx.x;
    if (i >= n4) return;
    float4 v = src[i];
    uint32_t h01, l01, h23, l23;
    split2(v.x, v.y, h01, l01);
    split2(v.z, v.w, h23, l23);
    *(uint2*)(dh + (size_t)i * 4) = make_uint2(h01, h23);
    *(uint2*)(dl + (size_t)i * 4) = make_uint2(l01, l23);
}
__global__ void conv_hi4(const float4* __restrict__ src, f16* __restrict__ dh,
                         int n4, int inner4, int gm, int go) {
    int i = blockIdx.x * blockDim.x + threadIdx.x;
    if (i >= n4) return;
    float4 v = src[i];
    size_t d = ((size_t)(i / inner4) * inner4 * gm + (size_t)go * inner4 + (i % inner4)) * 4;
    *(uint2*)(dh + d) = make_uint2(pack2h(v.x, v.y), pack2h(v.z, v.w));
}
__global__ void map_bias(const float* __restrict__ src, float* __restrict__ dst,
                         int n, int inner, int gm, int go) {
    int i = blockIdx.x * blockDim.x + threadIdx.x;
    if (i >= n) return;
    dst[(size_t)(i / inner) * inner * gm + (size_t)go * inner + (i % inner)] = src[i];
}

// ---------------- mask: detect dtype, canonicalize to u8 ----------------
__global__ void detect_mask_kernel(const void* m) {
    __shared__ int flags[2];
    if (threadIdx.x == 0) { flags[0] = 0; flags[1] = 0; }
    __syncthreads();
    unsigned v = ((const unsigned*)m)[threadIdx.x];
    if (v > 1u) flags[0] = 1;
    if (v != 0u && v != 0x3F800000u) flags[1] = 1;
    __syncthreads();
    if (threadIdx.x == 0)
        g_mask_mode = (!flags[0]) ? 1 : ((!flags[1]) ? 2 : 0);
}
__global__ void mask8_kernel(const void* m) {
    int i = blockIdx.x * blockDim.x + threadIdx.x;
    int mode = g_mask_mode;
    unsigned char r;
    if (mode == 1)      r = ((const int*)m)[i] != 0;
    else if (mode == 2) r = ((const float*)m)[i] != 0.f;
    else                r = ((const unsigned char*)m)[i] != 0;
    g_mask8[i] = r;
}

// ============================================================================
// fp16 HMMA GEMM: C = A[M,K] @ W[K,N]; A split (TERMS=2) or hi-only (TERMS=1),
// W hi-only always.
// MODE 0: C = acc+bias            MODE 1: C += acc+bias
// MODE 2: CH = f16(gelu(acc+bias))   (hi only)
// MODE 3: QKV: z=0 rope->qh/ql, z=1 rope->kh, z=2 ->vh
// ============================================================================
#define A_STRIDE   80
#define B_STRIDE   272
#define AH_OFF     0
#define AL_OFF     10240
#define BH_OFF     20480
#define STAGE_B    29184
#define GEMM_SMEM  (2*STAGE_B)

template<int TERMS>
__device__ __forceinline__ void load_stage(
    const f16* __restrict__ AH, const f16* __restrict__ AL,
    const f16* __restrict__ WH,
    int K, int N, int rowBase, int colBase, int ck, uint32_t st, int tid)
{
#pragma unroll
    for (int t = 0; t < (TERMS == 2 ? 4 : 2); t++) {
        int idx = tid + t * 256;
        int tile = idx >> 9;
        int r = (idx >> 2) & 127;
        int c16 = idx & 3;
        const f16* src = (tile ? AL : AH) + (size_t)(rowBase + r) * K + ck + c16 * 8;
        uint32_t dst = st + (tile ? AL_OFF : AH_OFF) + r * A_STRIDE + c16 * 16;
        CP_ASYNC(dst, src);
    }
#pragma unroll
    for (int t = 0; t < 2; t++) {
        int idx = tid + t * 256;
        int r = (idx >> 4) & 31;
        int c16 = idx & 15;
        const f16* src = WH + (size_t)(ck + r) * N + colBase + c16 * 8;
        uint32_t dst = st + BH_OFF + r * B_STRIDE + c16 * 16;
        CP_ASYNC(dst, src);
    }
}

template<int MODE, int TERMS>
__global__ void __launch_bounds__(256, 2) hmma2(
    const f16* __restrict__ AH, const f16* __restrict__ AL,
    const f16* __restrict__ WH,
    const float* __restrict__ bias, float* __restrict__ C,
    f16* __restrict__ CH, f16* __restrict__ CL,
    f16* __restrict__ o1h, f16* __restrict__ o2h,
    int M, int N, int K, long long Wz, long long bz)
{
    extern __shared__ char smem[];
    const int z = blockIdx.z;
    WH += (size_t)z * Wz; bias += (size_t)z * bz;

    const int tid  = threadIdx.x;
    const int lane = tid & 31;
    const int wid  = tid >> 5;
    const int m0   = (wid & 3) << 5;
    const int n0w  = (wid >> 2) << 6;
    const int rowBase = blockIdx.y << 7;
    const int colBase = blockIdx.x << 7;
    const int NC = K >> 5;

    uint32_t sbase = smem_u32(smem);

    float acc[2][8][4];
#pragma unroll
    for (int a = 0; a < 2; a++)
#pragma unroll
        for (int b = 0; b < 8; b++)
#pragma unroll
            for (int c = 0; c < 4; c++) acc[a][b][c] = 0.f;

    load_stage<TERMS>(AH, AL, WH, K, N, rowBase, colBase, 0, sbase, tid);
    CP_COMMIT();
    load_stage<TERMS>(AH, AL, WH, K, N, rowBase, colBase, 32, sbase + STAGE_B, tid);
    CP_COMMIT();
    CP_WAIT(1);
    __syncthreads();

    const int arow = lane & 15;
    const int aoff = (lane >> 4) << 4;

    for (int c = 0; c < NC; c++) {
        uint32_t cur = sbase + (c & 1) * STAGE_B;
#pragma unroll
        for (int ks = 0; ks < 32; ks += 16) {
            uint32_t ah[2][4], al[2][4];
#pragma unroll
            for (int mt = 0; mt < 2; mt++) {
                uint32_t ad = cur + (uint32_t)((m0 + mt * 16 + arow) * A_STRIDE + ks * 2 + aoff);
                ldsm4(ah[mt], ad);
                if (TERMS == 2) ldsm4(al[mt], ad + AL_OFF);
            }
#pragma unroll
            for (int np = 0; np < 4; np++) {
                uint32_t bh[4];
                uint32_t bd = cur + BH_OFF +
                    (uint32_t)((ks + arow) * B_STRIDE + ((n0w + np * 16) << 1) + aoff);
                ldsm4t(bh, bd);
#pragma unroll
                for (int mt = 0; mt < 2; mt++)
#pragma unroll
                    for (int e = 0; e < 2; e++) {
                        uint32_t bfh[2] = { bh[2 * e], bh[2 * e + 1] };
                        float* d = acc[mt][np * 2 + e];
                        mma16816(d, ah[mt], bfh);
                        if (TERMS == 2) mma16816(d, al[mt], bfh);
                    }
            }
        }
        __syncthreads();
        if (c + 2 < NC) {
            load_stage<TERMS>(AH, AL, WH, K, N, rowBase, colBase, (c + 2) << 5,
                              sbase + (c & 1) * STAGE_B, tid);
            CP_COMMIT();
            CP_WAIT(1);
        } else {
            CP_WAIT(0);
        }
        __syncthreads();
    }

    // ---- epilogue ----
    if (MODE == 3) {
#pragma unroll
        for (int mt = 0; mt < 2; mt++) {
#pragma unroll
            for (int half = 0; half < 2; half++) {
                const int row = rowBase + m0 + mt * 16 + (lane >> 2) + half * 8;
                const int s = row >> 2;
                if (z < 2) {
#pragma unroll
                    for (int nt = 0; nt < 4; nt++) {
                        const int c0 = colBase + n0w + (nt << 3) + ((lane & 3) << 1);
                        float v0 = acc[mt][nt][half * 2 + 0] + bias[c0];
                        float v1 = acc[mt][nt][half * 2 + 1] + bias[c0 + 1];
                        float w0 = acc[mt][nt + 4][half * 2 + 0] + bias[c0 + 32];
                        float w1 = acc[mt][nt + 4][half * 2 + 1] + bias[c0 + 33];
                        int i0 = c0 & 63;
                        float th0 = (float)s * expf(-0.28782313662425572f * (float)i0);
                        float th1 = (float)s * expf(-0.28782313662425572f * (float)(i0 + 1));
                        float c0s, s0s, c1s, s1s;
                        sincosf(th0, &s0s, &c0s);
                        sincosf(th1, &s1s, &c1s);
                        float y0 = v0 * c0s - w0 * s0s, zz0 = w0 * c0s + v0 * s0s;
                        float y1 = v1 * c1s - w1 * s1s, zz1 = w1 * c1s + v1 * s1s;
                        if (z == 0) {
                            uint32_t hi, lo;
                            split2(y0, y1, hi, lo);
                            *(uint32_t*)(CH + (size_t)row * D_ + c0) = hi;
                            *(uint32_t*)(CL + (size_t)row * D_ + c0) = lo;
                            split2(zz0, zz1, hi, lo);
                            *(uint32_t*)(CH + (size_t)row * D_ + c0 + 32) = hi;
                            *(uint32_t*)(CL + (size_t)row * D_ + c0 + 32) = lo;
                        } else {
                            *(uint32_t*)(o1h + (size_t)row * D_ + c0) = pack2h(y0, y1);
                            *(uint32_t*)(o1h + (size_t)row * D_ + c0 + 32) = pack2h(zz0, zz1);
                        }
                    }
                } else {
#pragma unroll
                    for (int nt = 0; nt < 8; nt++) {
                        const int c0 = colBase + n0w + (nt << 3) + ((lane & 3) << 1);
                        float v0 = acc[mt][nt][half * 2 + 0] + bias[c0];
                        float v1 = acc[mt][nt][half * 2 + 1] + bias[c0 + 1];
                        *(uint32_t*)(o2h + (size_t)row * D_ + c0) = pack2h(v0, v1);
                    }
                }
            }
        }
        return;
    }

#pragma unroll
    for (int mt = 0; mt < 2; mt++) {
        const int r0 = rowBase + m0 + mt * 16 + (lane >> 2);
#pragma unroll
        for (int nt = 0; nt < 8; nt++) {
            const int c0 = colBase + n0w + nt * 8 + ((lane & 3) << 1);
            float* d = acc[mt][nt];
            float b0 = bias[c0], b1 = bias[c0 + 1];
#pragma unroll
            for (int half = 0; half < 2; half++) {
                const int row = r0 + half * 8;
                float v0 = d[half * 2 + 0] + b0;
                float v1 = d[half * 2 + 1] + b1;
                if (MODE == 0) {
                    float* out = C + (size_t)row * N + c0;
                    out[0] = v0; out[1] = v1;
                } else if (MODE == 1) {
                    float* out = C + (size_t)row * N + c0;
                    out[0] += v0; out[1] += v1;
                } else {
                    float g0 = 0.5f * v0 * (1.f + erff(v0 * 0.70710678118654752f));
                    float g1 = 0.5f * v1 * (1.f + erff(v1 * 0.70710678118654752f));
                    *(uint32_t*)(CH + (size_t)row * N + c0) = pack2h(g0, g1);
                }
            }
        }
    }
}

// ============================================================================
// Flash attention (fp16 2-term): Q split, K/V hi-only.
// ============================================================================
#define FA_STRIDE 144
#define FA_TILE   18432
#define FA_SMEM   (6*FA_TILE)

__device__ __forceinline__ void fa_kv_load(
    const f16* __restrict__ kh, const f16* __restrict__ vh,
    size_t hoff, int krow0, uint32_t dst, int tid)
{
#pragma unroll
    for (int t = 0; t < 8; t++) {
        int idx = tid + t * 256;
        int tile = idx >> 10, rem = idx & 1023;
        int r = rem >> 3, c = rem & 7;
        const f16* base = tile ? vh : kh;
        const f16* src = base + hoff + (size_t)(krow0 + r) * (B_ * D_) + c * 8;
        CP_ASYNC(dst + tile * FA_TILE + r * FA_STRIDE + c * 16, src);
    }
}

__global__ void __launch_bounds__(256, 1) flash_attn(
    const f16* __restrict__ qh, const f16* __restrict__ ql,
    const f16* __restrict__ kh, const f16* __restrict__ vh,
    const unsigned char* __restrict__ mask8,
    f16* __restrict__ aH, f16* __restrict__ aL)
{
    extern __shared__ char smem[];
    const int bh = blockIdx.y;
    const int b = bh >> 4, h = bh & 15;
    const int q0 = blockIdx.x << 7;
    const int tid = threadIdx.x, lane = tid & 31, wid = tid >> 5;
    const int m0 = wid << 4;
    const size_t hoff = (size_t)b * D_ + h * HD_;
    uint32_t sb = smem_u32(smem);
    const uint32_t kv0 = sb + 2 * FA_TILE;
    const uint32_t kv1 = sb + 4 * FA_TILE;

#pragma unroll
    for (int t = 0; t < 8; t++) {
        int idx = tid + t * 256;
        int tile = idx >> 10, rem = idx & 1023;
        int r = rem >> 3, c = rem & 7;
        const f16* src = (tile ? ql : qh) + hoff + (size_t)(q0 + r) * (B_ * D_) + c * 8;
        CP_ASYNC(sb + tile * FA_TILE + r * FA_STRIDE + c * 16, src);
    }
    fa_kv_load(kh, vh, hoff, 0, kv0, tid);
    CP_COMMIT();
    fa_kv_load(kh, vh, hoff, 128, kv1, tid);
    CP_COMMIT();
    CP_WAIT(1);
    __syncthreads();

    float oacc[8][4];
#pragma unroll
    for (int i = 0; i < 8; i++)
#pragma unroll
        for (int j = 0; j < 4; j++) oacc[i][j] = 0.f;
    float mr0 = -1e30f, mr1 = -1e30f, l0 = 0.f, l1 = 0.f;

    const int arow = lane & 15;
    const int aoff = (lane >> 4) << 4;
    const unsigned char* mrow = mask8 + b * S_;

    for (int kt = 0; kt < 4; kt++) {
        const uint32_t kv = (kt & 1) ? kv1 : kv0;
        float sacc[16][4];
#pragma unroll
        for (int i = 0; i < 16; i++)
#pragma unroll
            for (int j = 0; j < 4; j++) sacc[i][j] = 0.f;

#pragma unroll
        for (int kc = 0; kc < 4; kc++) {
            uint32_t qa = sb + (uint32_t)((m0 + arow) * FA_STRIDE + kc * 32 + aoff);
            uint32_t qhf[4], qlf[4];
            ldsm4(qhf, qa);
            ldsm4(qlf, qa + FA_TILE);
#pragma unroll
            for (int ng = 0; ng < 8; ng++) {
                uint32_t bhf[4];
                uint32_t ka = kv + (uint32_t)((ng * 16 + arow) * FA_STRIDE + kc * 32 + aoff);
                ldsm4(bhf, ka);
#pragma unroll
                for (int e = 0; e < 2; e++) {
                    uint32_t bh2[2] = { bhf[e], bhf[e + 2] };
                    float* d = sacc[ng * 2 + e];
                    mma16816(d, qhf, bh2);
                    mma16816(d, qlf, bh2);
                }
            }
        }

        float mx0 = -1e30f, mx1 = -1e30f;
#pragma unroll
        for (int nt = 0; nt < 16; nt++) {
#pragma unroll
            for (int u = 0; u < 2; u++) {
                int col = (kt << 7) + (nt << 3) + ((lane & 3) << 1) + u;
                bool msk = mrow[col] != 0;
                float v0 = msk ? -1e30f : sacc[nt][u] * 0.125f;
                float v1 = msk ? -1e30f : sacc[nt][2 + u] * 0.125f;
                sacc[nt][u] = v0; sacc[nt][2 + u] = v1;
                mx0 = fmaxf(mx0, v0); mx1 = fmaxf(mx1, v1);
            }
        }
        mx0 = fmaxf(mx0, __shfl_xor_sync(0xFFFFFFFFu, mx0, 1));
        mx0 = fmaxf(mx0, __shfl_xor_sync(0xFFFFFFFFu, mx0, 2));
        mx1 = fmaxf(mx1, __shfl_xor_sync(0xFFFFFFFFu, mx1, 1));
        mx1 = fmaxf(mx1, __shfl_xor_sync(0xFFFFFFFFu, mx1, 2));
        float mn0 = fmaxf(mr0, mx0), mn1 = fmaxf(mr1, mx1);
        float al0 = __expf(mr0 - mn0), al1 = __expf(mr1 - mn1);
        mr0 = mn0; mr1 = mn1;

        float s0 = 0.f, s1 = 0.f;
#pragma unroll
        for (int nt = 0; nt < 16; nt++) {
            float p0 = __expf(sacc[nt][0] - mn0);
            float p1 = __expf(sacc[nt][1] - mn0);
            float p2 = __expf(sacc[nt][2] - mn1);
            float p3 = __expf(sacc[nt][3] - mn1);
            sacc[nt][0] = p0; sacc[nt][1] = p1; sacc[nt][2] = p2; sacc[nt][3] = p3;
            s0 += p0 + p1; s1 += p2 + p3;
        }
        s0 += __shfl_xor_sync(0xFFFFFFFFu, s0, 1);
        s0 += __shfl_xor_sync(0xFFFFFFFFu, s0, 2);
        s1 += __shfl_xor_sync(0xFFFFFFFFu, s1, 1);
        s1 += __shfl_xor_sync(0xFFFFFFFFu, s1, 2);
        l0 = l0 * al0 + s0;
        l1 = l1 * al1 + s1;
#pragma unroll
        for (int nt = 0; nt < 8; nt++) {
            oacc[nt][0] *= al0; oacc[nt][1] *= al0;
            oacc[nt][2] *= al1; oacc[nt][3] *= al1;
        }

#pragma unroll
        for (int kc2 = 0; kc2 < 8; kc2++) {
            uint32_t pa_h[4], pa_l[4];
            split2(sacc[2 * kc2][0],     sacc[2 * kc2][1],     pa_h[0], pa_l[0]);
            split2(sacc[2 * kc2][2],     sacc[2 * kc2][3],     pa_h[1], pa_l[1]);
            split2(sacc[2 * kc2 + 1][0], sacc[2 * kc2 + 1][1], pa_h[2], pa_l[2]);
            split2(sacc[2 * kc2 + 1][2], sacc[2 * kc2 + 1][3], pa_h[3], pa_l[3]);
#pragma unroll
            for (int ng = 0; ng < 4; ng++) {
                uint32_t bhf[4];
                uint32_t va = kv + FA_TILE +
                    (uint32_t)((kc2 * 16 + arow) * FA_STRIDE + ng * 32 + aoff);
                ldsm4t(bhf, va);
#pragma unroll
                for (int e = 0; e < 2; e++) {
                    uint32_t bh2[2] = { bhf[2 * e], bhf[2 * e + 1] };
                    float* d = oacc[ng * 2 + e];
                    mma16816(d, pa_h, bh2);
                    mma16816(d, pa_l, bh2);
                }
            }
        }

        __syncthreads();
        if (kt + 2 < 4) {
            fa_kv_load(kh, vh, hoff, (kt + 2) << 7, kv, tid);
            CP_COMMIT();
            CP_WAIT(1);
            __syncthreads();
        } else if (kt + 1 < 4) {
            CP_WAIT(0);
            __syncthreads();
        }
    }

    float inv0 = 1.f / l0, inv1 = 1.f / l1;
    const int r0 = q0 + m0 + (lane >> 2);
#pragma unroll
    for (int nt = 0; nt < 8; nt++) {
        const int c0 = (nt << 3) + ((lane & 3) << 1);
        uint32_t hi, lo;
        split2(oacc[nt][0] * inv0, oacc[nt][1] * inv0, hi, lo);
        size_t a0 = hoff + (size_t)r0 * (B_ * D_) + c0;
        *(uint32_t*)(aH + a0) = hi;
        *(uint32_t*)(aL + a0) = lo;
        split2(oacc[nt][2] * inv1, oacc[nt][3] * inv1, hi, lo);
        size_t a1 = hoff + (size_t)(r0 + 8) * (B_ * D_) + c0;
        *(uint32_t*)(aH + a1) = hi;
        *(uint32_t*)(aL + a1) = lo;
    }
}

// ---------------- LayerNorm -> split fp16, warp per row ----------------
__global__ __launch_bounds__(256) void ln_kernel(
    const float* __restrict__ x, const float* __restrict__ g,
    const float* __restrict__ b, f16* __restrict__ outH, f16* __restrict__ outL)
{
    const int lane = threadIdx.x & 31;
    const int wid  = threadIdx.x >> 5;
    const int row  = blockIdx.x * 8 + wid;
    const float* xr = x + (size_t)row * D_;
    float4 vv[8];
    float s = 0.f, s2 = 0.f;
#pragma unroll
    for (int k = 0; k < 8; k++) {
        vv[k] = *(const float4*)(xr + lane * 4 + k * 128);
        s  += vv[k].x + vv[k].y + vv[k].z + vv[k].w;
        s2 += vv[k].x * vv[k].x + vv[k].y * vv[k].y
            + vv[k].z * vv[k].z + vv[k].w * vv[k].w;
    }
#pragma unroll
    for (int o = 16; o; o >>= 1) {
        s  += __shfl_xor_sync(0xFFFFFFFFu, s,  o);
        s2 += __shfl_xor_sync(0xFFFFFFFFu, s2, o);
    }
    float mean = s * (1.f / D_);
    float var  = s2 * (1.f / D_) - mean * mean;
    float rstd = rsqrtf(var + 1e-5f);
#pragma unroll
    for (int k = 0; k < 8; k++) {
        int c0 = lane * 4 + k * 128;
        float4 gv = *(const float4*)(g + c0);
        float4 bv = *(const float4*)(b + c0);
        float o0 = (vv[k].x - mean) * rstd * gv.x + bv.x;
        float o1 = (vv[k].y - mean) * rstd * gv.y + bv.y;
        float o2 = (vv[k].z - mean) * rstd * gv.z + bv.z;
        float o3 = (vv[k].w - mean) * rstd * gv.w + bv.w;
        uint32_t h01, l01, h23, l23;
        split2(o0, o1, h01, l01);
        split2(o2, o3, h23, l23);
        *(uint2*)(outH + (size_t)row * D_ + c0) = make_uint2(h01, h23);
        *(uint2*)(outL + (size_t)row * D_ + c0) = make_uint2(l01, l23);
    }
}

// ---------------- x += dur[r]*Wdur[c] + bdur[c] ----------------
__global__ void adddur_kernel(float* __restrict__ x, const float* __restrict__ dur,
                              const float* __restrict__ wd, const float* __restrict__ bd) {
    int idx = blockIdx.x * blockDim.x + threadIdx.x;
    int r = idx >> 10, c = idx & 1023;
    x[idx] += dur[r] * wd[c] + bd[c];
}

// ---------------- host orchestration ----------------
extern "C" void kernel_launch(void* const* d_in, const int* in_sizes, int n_in,
                              void* d_out, int out_size)
{
    (void)in_sizes; (void)n_in; (void)out_size;
    const float* segments  = (const float*)d_in[0];
    const float* durations = (const float*)d_in[1];
    const void*  mask      = d_in[2];
    const float* Wproj = (const float*)d_in[3];
    const float* bproj = (const float*)d_in[4];
    const float* Wdur  = (const float*)d_in[5];
    const float* bdur  = (const float*)d_in[6];
    const float* ln1g  = (const float*)d_in[7];
    const float* ln1b  = (const float*)d_in[8];
    const float* Wq    = (const float*)d_in[9];
    const float* bq    = (const float*)d_in[10];
    const float* Wk    = (const float*)d_in[11];
    const float* bk    = (const float*)d_in[12];
    const float* Wv    = (const float*)d_in[13];
    const float* bv    = (const float*)d_in[14];
    const float* Wo    = (const float*)d_in[15];
    const float* bo    = (const float*)d_in[16];
    const float* ln2g  = (const float*)d_in[17];
    const float* ln2b  = (const float*)d_in[18];
    const float* W1    = (const float*)d_in[19];
    const float* b1    = (const float*)d_in[20];
    const float* W2    = (const float*)d_in[21];
    const float* b2    = (const float*)d_in[22];
    float* x = (float*)d_out;

    f16 *wqkvH, *woH, *w1H, *w2H, *wpH;
    f16 *segH, *segL, *hH, *hL, *aH, *aL, *ffH;
    f16 *qh, *ql, *kh, *vh;
    float *bqkv;
    unsigned char* mask8;
    cudaGetSymbolAddress((void**)&wqkvH, g_wqkv_h);
    cudaGetSymbolAddress((void**)&woH,   g_wo_h);
    cudaGetSymbolAddress((void**)&w1H,   g_w1_h);
    cudaGetSymbolAddress((void**)&w2H,   g_w2_h);
    cudaGetSymbolAddress((void**)&wpH,   g_wp_h);
    cudaGetSymbolAddress((void**)&segH,  g_seg_h);
    cudaGetSymbolAddress((void**)&segL,  g_seg_l);
    cudaGetSymbolAddress((void**)&hH,    g_hh);
    cudaGetSymbolAddress((void**)&hL,    g_hl);
    cudaGetSymbolAddress((void**)&aH,    g_ah);
    cudaGetSymbolAddress((void**)&aL,    g_al);
    cudaGetSymbolAddress((void**)&ffH,   g_ffh);
    cudaGetSymbolAddress((void**)&bqkv,  g_bqkv);
    cudaGetSymbolAddress((void**)&qh, g_qh);
    cudaGetSymbolAddress((void**)&ql, g_ql);
    cudaGetSymbolAddress((void**)&kh, g_kh);
    cudaGetSymbolAddress((void**)&vh, g_vh);
    cudaGetSymbolAddress((void**)&mask8, g_mask8);

    cudaFuncSetAttribute((const void*)hmma2<0,2>, cudaFuncAttributeMaxDynamicSharedMemorySize, GEMM_SMEM);
    cudaFuncSetAttribute((const void*)hmma2<1,2>, cudaFuncAttributeMaxDynamicSharedMemorySize, GEMM_SMEM);
    cudaFuncSetAttribute((const void*)hmma2<2,1>, cudaFuncAttributeMaxDynamicSharedMemorySize, GEMM_SMEM);
    cudaFuncSetAttribute((const void*)hmma2<1,1>, cudaFuncAttributeMaxDynamicSharedMemorySize, GEMM_SMEM);
    cudaFuncSetAttribute((const void*)hmma2<3,2>, cudaFuncAttributeMaxDynamicSharedMemorySize, GEMM_SMEM);
    cudaFuncSetAttribute((const void*)flash_attn, cudaFuncAttributeMaxDynamicSharedMemorySize, FA_SMEM);

    detect_mask_kernel<<<1, 512>>>(mask);
    mask8_kernel<<<8, 256>>>(mask);

    const int CT = 256;
    int n4;
    n4 = (L_ * DD_) / 4;
    conv_hi4<<<(n4 + CT - 1) / CT, CT>>>((const float4*)Wq, wqkvH, n4, DD_ / 4, 3, 0);
    conv_hi4<<<(n4 + CT - 1) / CT, CT>>>((const float4*)Wk, wqkvH, n4, DD_ / 4, 3, 1);
    conv_hi4<<<(n4 + CT - 1) / CT, CT>>>((const float4*)Wv, wqkvH, n4, DD_ / 4, 3, 2);
    conv_hi4<<<(n4 + CT - 1) / CT, CT>>>((const float4*)Wo, woH, n4, 1, 1, 0);
    n4 = (L_ * DF_) / 4;
    conv_hi4<<<(n4 + CT - 1) / CT, CT>>>((const float4*)W1, w1H, n4, 1, 1, 0);
    conv_hi4<<<(n4 + CT - 1) / CT, CT>>>((const float4*)W2, w2H, n4, 1, 1, 0);
    n4 = (DIN_ * D_) / 4;
    conv_hi4<<<(n4 + CT - 1) / CT, CT>>>((const float4*)Wproj, wpH, n4, 1, 1, 0);
    n4 = (SB_ * DIN_) / 4;
    conv_split4<<<(n4 + CT - 1) / CT, CT>>>((const float4*)segments, segH, segL, n4);
    int nb = L_ * D_;
    map_bias<<<(nb + CT - 1) / CT, CT>>>(bq, bqkv, nb, D_, 3, 0);
    map_bias<<<(nb + CT - 1) / CT, CT>>>(bk, bqkv, nb, D_, 3, 1);
    map_bias<<<(nb + CT - 1) / CT, CT>>>(bv, bqkv, nb, D_, 3, 2);

    dim3 gD(D_ / 128, SB_ / 128);
    dim3 gQKV(D_ / 128, SB_ / 128, 3);
    dim3 gF(F_ / 128, SB_ / 128);

    hmma2<0,2><<<gD, 256, GEMM_SMEM>>>(segH, segL, wpH, bproj, x,
        nullptr, nullptr, nullptr, nullptr, SB_, D_, DIN_, 0, 0);
    adddur_kernel<<<(SB_ * D_) / 256, 256>>>(x, durations, Wdur, bdur);

    for (int l = 0; l < L_; l++) {
        ln_kernel<<<SB_ / 8, 256>>>(x, ln1g + (size_t)l * D_, ln1b + (size_t)l * D_, hH, hL);
        hmma2<3,2><<<gQKV, 256, GEMM_SMEM>>>(hH, hL,
            wqkvH + (size_t)l * 3 * DD_,
            bqkv + (size_t)l * 3 * D_, nullptr,
            qh, ql, kh, vh,
            SB_, D_, D_, DD_, D_);
        flash_attn<<<dim3(4, BH_), 256, FA_SMEM>>>(qh, ql, kh, vh, mask8, aH, aL);
        hmma2<1,2><<<gD, 256, GEMM_SMEM>>>(aH, aL,
            woH + (size_t)l * DD_,
            bo + (size_t)l * D_, x,
            nullptr, nullptr, nullptr, nullptr, SB_, D_, D_, 0, 0);
        ln_kernel<<<SB_ / 8, 256>>>(x, ln2g + (size_t)l * D_, ln2b + (size_t)l * D_, hH, hL);
        hmma2<2,1><<<gF, 256, GEMM_SMEM>>>(hH, hL,
            w1H + (size_t)l * DF_,
            b1 + (size_t)l * F_, nullptr,
            ffH, nullptr, nullptr, nullptr, SB_, F_, D_, 0, 0);
        hmma2<1,1><<<gD, 256, GEMM_SMEM>>>(ffH, nullptr,
            w2H + (size_t)l * DF_,
            b2 + (size_t)l * D_, x,
            nullptr, nullptr, nullptr, nullptr, SB_, D_, F_, 0, 0);
    }
}